// round 14
// baseline (speedup 1.0000x reference)
#include <cuda_runtime.h>
#include <cuda_bf16.h>
#include <cstdint>

// ---------------------------------------------------------------------------
// PointGenerator: X_world = M_c @ [x*d, y*d, d, 1],  M = E_ @ n2r @ K_^-1 (3x4)
//   M[i] = { e_i0/f, -e_i1/f, -M[i].x*cx - M[i].y*cy - e_i2, e_i3 } ; w == 1
//
// R13: per-warp TMA pipeline, NSTAGES=4 (R9's depth-2 re-exposed TMA latency
// every iteration: 2 x ~300cyc cover < ~900cyc round trip). Dynamic smem
// 75KB, 3 blocks/SM, no block-wide sync in steady state.
// ---------------------------------------------------------------------------

#define MAX_CAMS  200
#define NTHREADS  256
#define WARPS     8
#define CHUNK     128
#define NSTAGES   4
#define PPT       4                    // CHUNK/32

#define CAM_BYTES   (MAX_CAMS * 3 * 16)            // 9600
#define STAGE_BYTES (CHUNK * 12 + CHUNK * 4)       // 2048 (pidx 1536 + depth 512)
#define STAGES_OFF  CAM_BYTES
#define MBAR_OFF    (STAGES_OFF + WARPS * NSTAGES * STAGE_BYTES)   // 75136
#define SMEM_BYTES  (MBAR_OFF + WARPS * NSTAGES * 8)               // 75392

__device__ __forceinline__ uint32_t smem_u32(const void* p) {
    uint32_t a;
    asm("{ .reg .u64 t; cvta.to.shared.u64 t, %1; cvt.u32.u64 %0, t; }"
        : "=r"(a) : "l"(p));
    return a;
}
__device__ __forceinline__ void mbar_init(uint32_t mbar, uint32_t cnt) {
    asm volatile("mbarrier.init.shared.b64 [%0], %1;" :: "r"(mbar), "r"(cnt) : "memory");
}
__device__ __forceinline__ void mbar_expect_tx(uint32_t mbar, uint32_t bytes) {
    asm volatile("mbarrier.arrive.expect_tx.shared.b64 _, [%0], %1;"
                 :: "r"(mbar), "r"(bytes) : "memory");
}
__device__ __forceinline__ void mbar_wait(uint32_t mbar, uint32_t parity) {
    uint32_t done;
    asm volatile(
        "{ .reg .pred p;\n"
        "  mbarrier.try_wait.parity.acquire.cta.shared::cta.b64 p, [%1], %2;\n"
        "  selp.b32 %0, 1, 0, p; }"
        : "=r"(done) : "r"(mbar), "r"(parity) : "memory");
    if (!done) {
        asm volatile(
            "{ .reg .pred P1;\n"
            "WAIT_%=:\n"
            "  mbarrier.try_wait.parity.acquire.cta.shared::cta.b64 P1, [%0], %1, 0x989680;\n"
            "  @P1 bra.uni DONE_%=;\n"
            "  bra.uni WAIT_%=;\n"
            "DONE_%=: }"
            :: "r"(mbar), "r"(parity) : "memory");
    }
}
__device__ __forceinline__ void bulk_load_g2s(uint32_t smem_dst, const void* gmem_src,
                                              uint32_t bytes, uint32_t mbar) {
    asm volatile(
        "cp.async.bulk.shared::cta.global.mbarrier::complete_tx::bytes [%0], [%1], %2, [%3];"
        :: "r"(smem_dst), "l"(gmem_src), "r"(bytes), "r"(mbar) : "memory");
}

__device__ __forceinline__ float4 transform(const float4* __restrict__ s_cam,
                                            int c, float xf, float yf, float dd) {
    float xd = xf * dd;
    float yd = yf * dd;
    float4 r0 = s_cam[c * 3 + 0];
    float4 r1 = s_cam[c * 3 + 1];
    float4 r2 = s_cam[c * 3 + 2];
    float4 o;
    o.x = fmaf(r0.x, xd, fmaf(r0.y, yd, fmaf(r0.z, dd, r0.w)));
    o.y = fmaf(r1.x, xd, fmaf(r1.y, yd, fmaf(r1.z, dd, r1.w)));
    o.z = fmaf(r2.x, xd, fmaf(r2.y, yd, fmaf(r2.z, dd, r2.w)));
    o.w = 1.0f;
    return o;
}

__global__ void __launch_bounds__(NTHREADS, 3)
point_gen_kernel(const int*   __restrict__ pidx,   // [N,3] i32
                 const float* __restrict__ depth,  // [N]   f32
                 const float* __restrict__ c2w,    // [C,3,4] f32
                 const float* __restrict__ intr,   // [C,3,3] f32
                 float*       __restrict__ out,    // [N,4] f32
                 int npoints, int num_cams, int nchunks) {
    extern __shared__ char dsm[];
    float4* s_cam = (float4*)dsm;

    const int tid  = threadIdx.x;
    const int wid  = tid >> 5;
    const int lane = tid & 31;
    const int gw     = blockIdx.x * WARPS + wid;
    const int stride = gridDim.x * WARPS;

    // this warp's stage ring base addresses
    const uint32_t dsm_base   = smem_u32(dsm);
    const uint32_t stage_base = dsm_base + STAGES_OFF + wid * NSTAGES * STAGE_BYTES;
    const uint32_t mbar_base  = dsm_base + MBAR_OFF + wid * NSTAGES * 8;

    // --- per-warp mbar init + prologue prefetch of NSTAGES chunks ---
    if (lane == 0) {
#pragma unroll
        for (int s = 0; s < NSTAGES; s++) mbar_init(mbar_base + s * 8, 1);
        asm volatile("fence.proxy.async.shared::cta;" ::: "memory");
#pragma unroll
        for (int s = 0; s < NSTAGES; s++) {
            int chunk = gw + s * stride;
            if (chunk < nchunks) {
                int base = chunk * CHUNK;
                int pts  = npoints - base; if (pts > CHUNK) pts = CHUNK;
                int bulk = pts & ~3;
                if (bulk > 0) {
                    uint32_t mb = mbar_base + s * 8;
                    uint32_t sp = stage_base + s * STAGE_BYTES;
                    mbar_expect_tx(mb, (uint32_t)bulk * 16u);
                    bulk_load_g2s(sp, pidx + (size_t)base * 3, (uint32_t)bulk * 12u, mb);
                    bulk_load_g2s(sp + CHUNK * 12, depth + base, (uint32_t)bulk * 4u, mb);
                }
            }
        }
    }

    // --- camera matrices once per block (overlaps prologue TMA) ---
    const float4* c2w4 = (const float4*)c2w;
    for (int c = tid; c < num_cams; c += NTHREADS) {
        float f  = __ldg(intr + c * 9 + 0);
        float cx = __ldg(intr + c * 9 + 2);
        float cy = __ldg(intr + c * 9 + 5);
        float invf = 1.0f / f;
#pragma unroll
        for (int i = 0; i < 3; i++) {
            float4 e = c2w4[c * 3 + i];        // {e0, e1, e2, t}
            float4 r;
            r.x = e.x * invf;
            r.y = -e.y * invf;
            r.z = fmaf(-r.x, cx, fmaf(-r.y, cy, -e.z));
            r.w = e.w;
            s_cam[c * 3 + i] = r;
        }
    }
    __syncthreads();   // cameras ready; only block-wide sync

    float4* out4 = (float4*)out;
    uint32_t par = 0;   // parity bitmask, bit s = phase of stage s
    int s = 0;

    for (int chunk = gw; chunk < nchunks; chunk += stride) {
        int base = chunk * CHUNK;
        int pts  = npoints - base; if (pts > CHUNK) pts = CHUNK;
        int bulk = pts & ~3;

        uint32_t mb = mbar_base + s * 8;
        uint32_t sp = stage_base + s * STAGE_BYTES;
        if (bulk > 0) {
            mbar_wait(mb, (par >> s) & 1u);
            par ^= (1u << s);
        }

        const int*   stp = (const int*)(dsm + (sp - dsm_base));
        const float* std_ = (const float*)(dsm + (sp - dsm_base) + CHUNK * 12);

        if (pts == CHUNK) {
#pragma unroll
            for (int j = 0; j < PPT; j += 2) {
                int p0 = lane + (j + 0) * 32;
                int p1 = lane + (j + 1) * 32;
                int   c0 = stp[3 * p0 + 0];
                int   c1 = stp[3 * p1 + 0];
                float y0 = (float)stp[3 * p0 + 1];
                float y1 = (float)stp[3 * p1 + 1];
                float x0 = (float)stp[3 * p0 + 2];
                float x1 = (float)stp[3 * p1 + 2];
                float d0 = std_[p0];
                float d1 = std_[p1];
                float4 o0 = transform(s_cam, c0, x0, y0, d0);
                float4 o1 = transform(s_cam, c1, x1, y1, d1);
                out4[base + p0] = o0;
                out4[base + p1] = o1;
            }
        } else {
            // partial last chunk
#pragma unroll
            for (int j = 0; j < PPT; j++) {
                int p = lane + j * 32;
                if (p < bulk) {
                    int   c  = stp[3 * p + 0];
                    float yf = (float)stp[3 * p + 1];
                    float xf = (float)stp[3 * p + 2];
                    out4[base + p] = transform(s_cam, c, xf, yf, std_[p]);
                }
            }
            for (int p = base + bulk + lane; p < base + pts; p += 32) {
                int   c  = pidx[3 * p + 0];
                float yf = (float)pidx[3 * p + 1];
                float xf = (float)pidx[3 * p + 2];
                out4[p] = transform(s_cam, c, xf, yf, depth[p]);
            }
        }

        __syncwarp();   // lanes done reading stage s before refill

        int nchunk = chunk + NSTAGES * stride;
        if (lane == 0 && nchunk < nchunks) {
            int nbase = nchunk * CHUNK;
            int npts  = npoints - nbase; if (npts > CHUNK) npts = CHUNK;
            int nbulk = npts & ~3;
            if (nbulk > 0) {
                mbar_expect_tx(mb, (uint32_t)nbulk * 16u);
                bulk_load_g2s(sp, pidx + (size_t)nbase * 3, (uint32_t)nbulk * 12u, mb);
                bulk_load_g2s(sp + CHUNK * 12, depth + nbase, (uint32_t)nbulk * 4u, mb);
            }
        }
        s = (s + 1) & (NSTAGES - 1);
    }
}

extern "C" void kernel_launch(void* const* d_in, const int* in_sizes, int n_in,
                              void* d_out, int out_size) {
    // metadata order: point_indices[N,3] i32, depth[N,1] f32, image_coords (unused),
    //                 camera_to_worlds[C,3,4] f32, intrinsics[C,3,3] f32
    const int*   pidx  = (const int*)d_in[0];
    const float* depth = (const float*)d_in[1];
    const float* c2w   = (const float*)d_in[3];
    const float* intr  = (const float*)d_in[4];
    float*       out   = (float*)d_out;

    int npoints  = in_sizes[0] / 3;
    int num_cams = in_sizes[3] / 12;
    if (num_cams > MAX_CAMS) num_cams = MAX_CAMS;

    static int smem_configured = 0;
    if (!smem_configured) {
        cudaFuncSetAttribute(point_gen_kernel,
                             cudaFuncAttributeMaxDynamicSharedMemorySize, SMEM_BYTES);
        smem_configured = 1;
    }

    int nchunks = (npoints + CHUNK - 1) / CHUNK;
    int blocks  = 148 * 3;
    int maxb    = (nchunks + WARPS - 1) / WARPS;
    if (blocks > maxb) blocks = maxb;
    point_gen_kernel<<<blocks, NTHREADS, SMEM_BYTES>>>(pidx, depth, c2w, intr, out,
                                                       npoints, num_cams, nchunks);
}

// round 15
// speedup vs baseline: 1.0133x; 1.0133x over previous
#include <cuda_runtime.h>
#include <cuda_bf16.h>
#include <cstdint>

// ---------------------------------------------------------------------------
// PointGenerator: X_world = M_c @ [x*d, y*d, d, 1],  M = E_ @ n2r @ K_^-1 (3x4)
//   M[i] = { e_i0/f, -e_i1/f, -M[i].x*cx - M[i].y*cy - e_i2, e_i3 } ; w == 1
//
// R14: per-warp pipeline, CHUNK=256 (halve per-chunk mbar/sync tax),
// NSTAGES=2, refill issued BEFORE compute (inputs drained to registers
// first) so the TMA overlaps the current chunk's ~700cyc of compute.
// ---------------------------------------------------------------------------

#define MAX_CAMS  200
#define NTHREADS  256
#define WARPS     8
#define CHUNK     256
#define NSTAGES   2
#define PPT       8                      // CHUNK/32

#define CAM_BYTES   (MAX_CAMS * 3 * 16)            // 9600
#define STAGE_BYTES (CHUNK * 12 + CHUNK * 4)       // 4096
#define STAGES_OFF  CAM_BYTES
#define MBAR_OFF    (STAGES_OFF + WARPS * NSTAGES * STAGE_BYTES)   // 75136
#define SMEM_BYTES  (MBAR_OFF + WARPS * NSTAGES * 8)               // 75264

__device__ __forceinline__ uint32_t smem_u32(const void* p) {
    uint32_t a;
    asm("{ .reg .u64 t; cvta.to.shared.u64 t, %1; cvt.u32.u64 %0, t; }"
        : "=r"(a) : "l"(p));
    return a;
}
__device__ __forceinline__ void mbar_init(uint32_t mbar, uint32_t cnt) {
    asm volatile("mbarrier.init.shared.b64 [%0], %1;" :: "r"(mbar), "r"(cnt) : "memory");
}
__device__ __forceinline__ void mbar_expect_tx(uint32_t mbar, uint32_t bytes) {
    asm volatile("mbarrier.arrive.expect_tx.shared.b64 _, [%0], %1;"
                 :: "r"(mbar), "r"(bytes) : "memory");
}
__device__ __forceinline__ void mbar_wait(uint32_t mbar, uint32_t parity) {
    uint32_t done;
    asm volatile(
        "{ .reg .pred p;\n"
        "  mbarrier.try_wait.parity.acquire.cta.shared::cta.b64 p, [%1], %2;\n"
        "  selp.b32 %0, 1, 0, p; }"
        : "=r"(done) : "r"(mbar), "r"(parity) : "memory");
    if (!done) {
        asm volatile(
            "{ .reg .pred P1;\n"
            "WAIT_%=:\n"
            "  mbarrier.try_wait.parity.acquire.cta.shared::cta.b64 P1, [%0], %1, 0x989680;\n"
            "  @P1 bra.uni DONE_%=;\n"
            "  bra.uni WAIT_%=;\n"
            "DONE_%=: }"
            :: "r"(mbar), "r"(parity) : "memory");
    }
}
__device__ __forceinline__ void bulk_load_g2s(uint32_t smem_dst, const void* gmem_src,
                                              uint32_t bytes, uint32_t mbar) {
    asm volatile(
        "cp.async.bulk.shared::cta.global.mbarrier::complete_tx::bytes [%0], [%1], %2, [%3];"
        :: "r"(smem_dst), "l"(gmem_src), "r"(bytes), "r"(mbar) : "memory");
}

__device__ __forceinline__ float4 transform(const float4* __restrict__ s_cam,
                                            int c, float xf, float yf, float dd) {
    float xd = xf * dd;
    float yd = yf * dd;
    float4 r0 = s_cam[c * 3 + 0];
    float4 r1 = s_cam[c * 3 + 1];
    float4 r2 = s_cam[c * 3 + 2];
    float4 o;
    o.x = fmaf(r0.x, xd, fmaf(r0.y, yd, fmaf(r0.z, dd, r0.w)));
    o.y = fmaf(r1.x, xd, fmaf(r1.y, yd, fmaf(r1.z, dd, r1.w)));
    o.z = fmaf(r2.x, xd, fmaf(r2.y, yd, fmaf(r2.z, dd, r2.w)));
    o.w = 1.0f;
    return o;
}

__global__ void __launch_bounds__(NTHREADS, 3)
point_gen_kernel(const int*   __restrict__ pidx,   // [N,3] i32
                 const float* __restrict__ depth,  // [N]   f32
                 const float* __restrict__ c2w,    // [C,3,4] f32
                 const float* __restrict__ intr,   // [C,3,3] f32
                 float*       __restrict__ out,    // [N,4] f32
                 int npoints, int num_cams, int nchunks) {
    extern __shared__ char dsm[];
    float4* s_cam = (float4*)dsm;

    const int tid  = threadIdx.x;
    const int wid  = tid >> 5;
    const int lane = tid & 31;
    const int gw     = blockIdx.x * WARPS + wid;
    const int stride = gridDim.x * WARPS;

    const uint32_t dsm_base   = smem_u32(dsm);
    const uint32_t stage_base = dsm_base + STAGES_OFF + wid * NSTAGES * STAGE_BYTES;
    const uint32_t mbar_base  = dsm_base + MBAR_OFF + wid * NSTAGES * 8;

    // --- per-warp mbar init + prologue prefetch of NSTAGES chunks ---
    if (lane == 0) {
#pragma unroll
        for (int s = 0; s < NSTAGES; s++) mbar_init(mbar_base + s * 8, 1);
        asm volatile("fence.proxy.async.shared::cta;" ::: "memory");
#pragma unroll
        for (int s = 0; s < NSTAGES; s++) {
            int chunk = gw + s * stride;
            if (chunk < nchunks) {
                int base = chunk * CHUNK;
                int pts  = npoints - base; if (pts > CHUNK) pts = CHUNK;
                int bulk = pts & ~3;
                if (bulk > 0) {
                    uint32_t mb = mbar_base + s * 8;
                    uint32_t sp = stage_base + s * STAGE_BYTES;
                    mbar_expect_tx(mb, (uint32_t)bulk * 16u);
                    bulk_load_g2s(sp, pidx + (size_t)base * 3, (uint32_t)bulk * 12u, mb);
                    bulk_load_g2s(sp + CHUNK * 12, depth + base, (uint32_t)bulk * 4u, mb);
                }
            }
        }
    }

    // --- camera matrices once per block (overlaps prologue TMA) ---
    const float4* c2w4 = (const float4*)c2w;
    for (int c = tid; c < num_cams; c += NTHREADS) {
        float f  = __ldg(intr + c * 9 + 0);
        float cx = __ldg(intr + c * 9 + 2);
        float cy = __ldg(intr + c * 9 + 5);
        float invf = 1.0f / f;
#pragma unroll
        for (int i = 0; i < 3; i++) {
            float4 e = c2w4[c * 3 + i];        // {e0, e1, e2, t}
            float4 r;
            r.x = e.x * invf;
            r.y = -e.y * invf;
            r.z = fmaf(-r.x, cx, fmaf(-r.y, cy, -e.z));
            r.w = e.w;
            s_cam[c * 3 + i] = r;
        }
    }
    __syncthreads();   // cameras ready; only block-wide sync

    float4* out4 = (float4*)out;
    uint32_t par = 0;   // parity bit per stage
    int s = 0;

    for (int chunk = gw; chunk < nchunks; chunk += stride) {
        int base = chunk * CHUNK;
        int pts  = npoints - base; if (pts > CHUNK) pts = CHUNK;
        int bulk = pts & ~3;

        uint32_t mb = mbar_base + s * 8;
        uint32_t sp_off = STAGES_OFF + wid * NSTAGES * STAGE_BYTES + s * STAGE_BYTES;
        const int*   stp  = (const int*)(dsm + sp_off);
        const float* std_ = (const float*)(dsm + sp_off + CHUNK * 12);

        if (bulk > 0) {
            mbar_wait(mb, (par >> s) & 1u);
            par ^= (1u << s);
        }

        if (pts == CHUNK) {
            // 1) drain ALL inputs to registers (frees the stage)
            int   cs[PPT];
            float ys[PPT], xs[PPT], ds[PPT];
#pragma unroll
            for (int j = 0; j < PPT; j++) {
                int p = lane + j * 32;
                cs[j] = stp[3 * p + 0];
                ys[j] = (float)stp[3 * p + 1];
                xs[j] = (float)stp[3 * p + 2];
                ds[j] = std_[p];
            }
            __syncwarp();

            // 2) refill stage s NOW -> TMA overlaps this chunk's compute
            int nchunk = chunk + NSTAGES * stride;
            if (lane == 0 && nchunk < nchunks) {
                int nbase = nchunk * CHUNK;
                int npts  = npoints - nbase; if (npts > CHUNK) npts = CHUNK;
                int nbulk = npts & ~3;
                if (nbulk > 0) {
                    uint32_t sp = stage_base + s * STAGE_BYTES;
                    mbar_expect_tx(mb, (uint32_t)nbulk * 16u);
                    bulk_load_g2s(sp, pidx + (size_t)nbase * 3,
                                  (uint32_t)nbulk * 12u, mb);
                    bulk_load_g2s(sp + CHUNK * 12, depth + nbase,
                                  (uint32_t)nbulk * 4u, mb);
                }
            }

            // 3) compute + store (2-point batching for gather overlap)
#pragma unroll
            for (int j = 0; j < PPT; j += 2) {
                float4 o0 = transform(s_cam, cs[j],     xs[j],     ys[j],     ds[j]);
                float4 o1 = transform(s_cam, cs[j + 1], xs[j + 1], ys[j + 1], ds[j + 1]);
                out4[base + lane + (j + 0) * 32] = o0;
                out4[base + lane + (j + 1) * 32] = o1;
            }
        } else {
            // partial last chunk (predicated, rare)
#pragma unroll
            for (int j = 0; j < PPT; j++) {
                int p = lane + j * 32;
                if (p < bulk) {
                    int   c  = stp[3 * p + 0];
                    float yf = (float)stp[3 * p + 1];
                    float xf = (float)stp[3 * p + 2];
                    out4[base + p] = transform(s_cam, c, xf, yf, std_[p]);
                }
            }
            for (int p = base + bulk + lane; p < base + pts; p += 32) {
                int   c  = pidx[3 * p + 0];
                float yf = (float)pidx[3 * p + 1];
                float xf = (float)pidx[3 * p + 2];
                out4[p] = transform(s_cam, c, xf, yf, depth[p]);
            }
            __syncwarp();
        }

        s ^= 1;
    }
}

extern "C" void kernel_launch(void* const* d_in, const int* in_sizes, int n_in,
                              void* d_out, int out_size) {
    // metadata order: point_indices[N,3] i32, depth[N,1] f32, image_coords (unused),
    //                 camera_to_worlds[C,3,4] f32, intrinsics[C,3,3] f32
    const int*   pidx  = (const int*)d_in[0];
    const float* depth = (const float*)d_in[1];
    const float* c2w   = (const float*)d_in[3];
    const float* intr  = (const float*)d_in[4];
    float*       out   = (float*)d_out;

    int npoints  = in_sizes[0] / 3;
    int num_cams = in_sizes[3] / 12;
    if (num_cams > MAX_CAMS) num_cams = MAX_CAMS;

    static int smem_configured = 0;
    if (!smem_configured) {
        cudaFuncSetAttribute(point_gen_kernel,
                             cudaFuncAttributeMaxDynamicSharedMemorySize, SMEM_BYTES);
        smem_configured = 1;
    }

    int nchunks = (npoints + CHUNK - 1) / CHUNK;
    int blocks  = 148 * 3;
    int maxb    = (nchunks + WARPS - 1) / WARPS;
    if (blocks > maxb) blocks = maxb;
    point_gen_kernel<<<blocks, NTHREADS, SMEM_BYTES>>>(pidx, depth, c2w, intr, out,
                                                       npoints, num_cams, nchunks);
}